// round 15
// baseline (speedup 1.0000x reference)
#include <cuda_runtime.h>
#include <cuda_bf16.h>
#include <math.h>
#include <stdint.h>

#define NN   100000
#define EE   1600000
#define DD   128
#define GG   128
#define LL   4
#define NCLS 10
#define EPSV 1e-5f
#define NB   391          // ceil(NN/256) scan blocks

// ---------------- scratch (static device globals; no allocation) ----------------
static __device__ __align__(16) float g_h [(size_t)NN * DD];   // GEMM output (gather source)
static __device__ __align__(16) float g_h2[(size_t)NN * DD];   // SpMM output
static __device__ __align__(16) float g_pool[GG * DD];         // pooled sums
static __device__ __align__(16) float g_dis[NN];
static __device__ __align__(8)  int2  g_edge[EE];              // {col, weight-as-int}
static __device__ __align__(16) __nv_bfloat16 g_wth[DD * DD];  // W^T hi  [n][k]
static __device__ __align__(16) __nv_bfloat16 g_wtl[DD * DD];  // W^T lo  [n][k]
static __device__ int   g_batch[NN];
static __device__ int   g_cnt[NN];
static __device__ int   g_fill[NN];
static __device__ int   g_rowptr[NN + 1];
static __device__ int   g_gptr[GG + 1];
static __device__ int   g_part[NB];
static __device__ int   g_i64;

// ---------------- mma helpers (standard PTX, sm_80+, fine on compute_103) --------
__device__ __forceinline__ void ldsm4(uint32_t r[4], uint32_t addr) {
    asm volatile("ldmatrix.sync.aligned.m8n8.x4.shared.b16 {%0,%1,%2,%3}, [%4];"
                 : "=r"(r[0]), "=r"(r[1]), "=r"(r[2]), "=r"(r[3]) : "r"(addr));
}
__device__ __forceinline__ void mma_bf16(float c[4], const uint32_t a[4], const uint32_t b[2]) {
    asm volatile("mma.sync.aligned.m16n8k16.row.col.f32.bf16.bf16.f32 "
                 "{%0,%1,%2,%3}, {%4,%5,%6,%7}, {%8,%9}, {%0,%1,%2,%3};"
                 : "+f"(c[0]), "+f"(c[1]), "+f"(c[2]), "+f"(c[3])
                 : "r"(a[0]), "r"(a[1]), "r"(a[2]), "r"(a[3]), "r"(b[0]), "r"(b[1]));
}
__device__ __forceinline__ uint32_t smem_u32(const void* p) {
    return (uint32_t)__cvta_generic_to_shared(p);
}
__device__ __forceinline__ uint32_t pack2(float f0, float f1) {
    __nv_bfloat16 h0 = __float2bfloat16(f0), h1 = __float2bfloat16(f1);
    return ((uint32_t)__bfloat16_as_ushort(h1) << 16) | __bfloat16_as_ushort(h0);
}
__device__ __forceinline__ uint32_t pack2lo(float f0, float f1) {
    __nv_bfloat16 h0 = __float2bfloat16(f0), h1 = __float2bfloat16(f1);
    float l0 = f0 - __bfloat162float(h0), l1 = f1 - __bfloat162float(h1);
    __nv_bfloat16 g0 = __float2bfloat16(l0), g1 = __float2bfloat16(l1);
    return ((uint32_t)__bfloat16_as_ushort(g1) << 16) | __bfloat16_as_ushort(g0);
}

// ---------------- dtype detection: int64 vs int32 index buffers ----------------
__global__ void k_detect(const int* __restrict__ eiw) {
    __shared__ int bad;
    if (threadIdx.x == 0) bad = 0;
    __syncthreads();
    for (int i = threadIdx.x; i < 2048; i += blockDim.x)
        if (eiw[2 * i + 1] != 0) bad = 1;
    __syncthreads();
    if (threadIdx.x == 0) g_i64 = bad ? 0 : 1;
}

// ---------------- preprocessing ----------------
__global__ void k_init() {
    int i = blockIdx.x * blockDim.x + threadIdx.x;
    int stride = gridDim.x * blockDim.x;
    for (int n = i; n < NN; n += stride) { g_cnt[n] = 0; g_fill[n] = 0; }
}

__global__ void k_hist(const void* __restrict__ ei) {
    int e = blockIdx.x * blockDim.x + threadIdx.x;
    if (e >= EE) return;
    int d = g_i64 ? (int)((const long long*)ei)[EE + e] : ((const int*)ei)[EE + e];
    if ((unsigned)d >= NN) d = 0;
    atomicAdd(&g_cnt[d], 1);
}

// batch is sorted: derive g_gptr from boundaries, no atomics.
__global__ void k_cvt_batch(const void* __restrict__ batch) {
    int n = blockIdx.x * blockDim.x + threadIdx.x;
    if (n >= NN) return;
    int b, bp = -1;
    if (g_i64) {
        const long long* p = (const long long*)batch;
        b = (int)p[n];
        if (n > 0) bp = (int)p[n - 1];
    } else {
        const int* p = (const int*)batch;
        b = p[n];
        if (n > 0) bp = p[n - 1];
    }
    if ((unsigned)b >= GG) b = 0;
    if (n > 0 && (unsigned)bp >= GG) bp = 0;
    g_batch[n] = b;
    if (b != bp)
        for (int g = bp + 1; g <= b; g++) g_gptr[g] = n;
    if (n == NN - 1)
        for (int g = b + 1; g <= GG; g++) g_gptr[g] = NN;
}

// ---------------- parallel 3-step scan (also computes dis = rsqrt(deg)) -----------
__global__ void k_scan1() {
    __shared__ int sh[256];
    int b = blockIdx.x, t = threadIdx.x;
    int i = b * 256 + t;
    int v = (i < NN) ? g_cnt[i] : 0;
    if (i < NN) g_dis[i] = rsqrtf((float)(v + 1));
    sh[t] = v;
    __syncthreads();
    for (int o = 128; o > 0; o >>= 1) {
        if (t < o) sh[t] += sh[t + o];
        __syncthreads();
    }
    if (t == 0) g_part[b] = sh[0];
}
__global__ void k_scan2() {
    if (threadIdx.x == 0) {
        int r = 0;
        for (int i = 0; i < NB; i++) { int v = g_part[i]; g_part[i] = r; r += v; }
        g_rowptr[NN] = EE;
    }
}
__global__ void k_scan3() {
    __shared__ int sh[256];
    int b = blockIdx.x, t = threadIdx.x;
    int i = b * 256 + t;
    int v = (i < NN) ? g_cnt[i] : 0;
    sh[t] = v;
    __syncthreads();
    for (int o = 1; o < 256; o <<= 1) {
        int x = (t >= o) ? sh[t - o] : 0;
        __syncthreads();
        sh[t] += x;
        __syncthreads();
    }
    if (i < NN) g_rowptr[i] = g_part[b] + sh[t] - v;
}

__global__ void k_scatter(const void* __restrict__ ei) {
    int e = blockIdx.x * blockDim.x + threadIdx.x;
    if (e >= EE) return;
    int s, d;
    if (g_i64) {
        const long long* p = (const long long*)ei;
        s = (int)p[e]; d = (int)p[EE + e];
    } else {
        const int* p = (const int*)ei;
        s = p[e]; d = p[EE + e];
    }
    if ((unsigned)s >= NN) s = 0;
    if ((unsigned)d >= NN) d = 0;
    int pos = g_rowptr[d] + atomicAdd(&g_fill[d], 1);
    g_edge[pos] = make_int2(s, __float_as_int(g_dis[s] * g_dis[d]));
}

// ---------------- W -> bf16 hi/lo transposed images [n][k] ----------------
__global__ void k_wconv(const float* __restrict__ W) {
    int i = blockIdx.x * 256 + threadIdx.x;
    if (i >= DD * DD) return;
    int n = i >> 7, k = i & 127;
    float w = W[k * DD + n];
    __nv_bfloat16 h = __float2bfloat16(w);
    __nv_bfloat16 l = __float2bfloat16(w - __bfloat162float(h));
    g_wth[i] = h;    // coalesced along k
    g_wtl[i] = l;
}

// ---------------- GEMM: g_h = X @ W via mma.sync bf16 hi/lo 3-split ----------------
// 256 thr (8 warps: 4m x 2n), 128 rows x 128 cols per block, K chunked x32.
// launch_bounds(.,2): cap regs at 128 -> 2 CTAs/SM for latency hiding.
#define LDAB 40   // bf16 row stride (80 B): conflict-free ldmatrix phases
__global__ void __launch_bounds__(256, 2) k_gemm_mma(const float* __restrict__ X) {
    __shared__ __align__(16) __nv_bfloat16 sAh[128][LDAB];
    __shared__ __align__(16) __nv_bfloat16 sAl[128][LDAB];
    __shared__ __align__(16) __nv_bfloat16 sBh[128][LDAB];
    __shared__ __align__(16) __nv_bfloat16 sBl[128][LDAB];
    int tid = threadIdx.x, lane = tid & 31, wid = tid >> 5;
    int row0 = blockIdx.x * 128;
    int m_base = (wid & 3) * 32;
    int n_base = (wid >> 2) * 64;

    float acc[2][8][4];
    #pragma unroll
    for (int i = 0; i < 2; i++)
        #pragma unroll
        for (int j = 0; j < 8; j++)
            #pragma unroll
            for (int q = 0; q < 4; q++) acc[i][j][q] = 0.f;

    // per-lane ldmatrix base addresses
    int li = lane & 7, mi = lane >> 3;
    uint32_t aAh = smem_u32(&sAh[m_base + (mi & 1) * 8 + li][(mi >> 1) * 8]);
    uint32_t aAl = smem_u32(&sAl[m_base + (mi & 1) * 8 + li][(mi >> 1) * 8]);
    uint32_t aBh = smem_u32(&sBh[n_base + (mi >> 1) * 8 + li][(mi & 1) * 8]);
    uint32_t aBl = smem_u32(&sBl[n_base + (mi >> 1) * 8 + li][(mi & 1) * 8]);

    const float4* X4 = (const float4*)X;
    for (int kc = 0; kc < 4; kc++) {
        __syncthreads();
        // A: load 128x32 fp32 chunk, convert to bf16 hi/lo
        #pragma unroll
        for (int it = 0; it < 4; it++) {
            int t4 = tid + it * 256;            // 1024 float4
            int r = t4 >> 3, c4 = t4 & 7;
            int m = row0 + r;
            float4 v = make_float4(0.f, 0.f, 0.f, 0.f);
            if (m < NN) v = X4[(size_t)m * 32 + kc * 8 + c4];
            uint2 hi, lo;
            hi.x = pack2(v.x, v.y);  hi.y = pack2(v.z, v.w);
            lo.x = pack2lo(v.x, v.y); lo.y = pack2lo(v.z, v.w);
            *(uint2*)((char*)&sAh[0][0] + r * (LDAB * 2) + c4 * 8) = hi;
            *(uint2*)((char*)&sAl[0][0] + r * (LDAB * 2) + c4 * 8) = lo;
        }
        // B: linear copy of pre-transposed images
        #pragma unroll
        for (int it = 0; it < 2; it++) {
            int t2 = tid + it * 256;            // 512 uint4
            int n = t2 >> 2, q = t2 & 3;
            *(uint4*)((char*)&sBh[0][0] + n * (LDAB * 2) + q * 16) =
                ((const uint4*)g_wth)[n * 16 + kc * 4 + q];
            *(uint4*)((char*)&sBl[0][0] + n * (LDAB * 2) + q * 16) =
                ((const uint4*)g_wtl)[n * 16 + kc * 4 + q];
        }
        __syncthreads();

        #pragma unroll
        for (int ks = 0; ks < 2; ks++) {
            int k0b = ks * 32;                  // bytes (16 bf16)
            uint32_t ah[2][4], al[2][4];
            ldsm4(ah[0], aAh + k0b);
            ldsm4(ah[1], aAh + 16 * (LDAB * 2) + k0b);
            ldsm4(al[0], aAl + k0b);
            ldsm4(al[1], aAl + 16 * (LDAB * 2) + k0b);
            #pragma unroll
            for (int grp = 0; grp < 2; grp++) {
                uint32_t bh[4][2], bl[4][2];
                uint32_t off = grp * 32 * (LDAB * 2) + k0b;
                ldsm4(&bh[0][0], aBh + off);
                ldsm4(&bh[2][0], aBh + off + 16 * (LDAB * 2));
                ldsm4(&bl[0][0], aBl + off);
                ldsm4(&bl[2][0], aBl + off + 16 * (LDAB * 2));
                #pragma unroll
                for (int mt = 0; mt < 2; mt++)
                    #pragma unroll
                    for (int nt = 0; nt < 4; nt++) {
                        float* c = acc[mt][grp * 4 + nt];
                        mma_bf16(c, ah[mt], bh[nt]);
                        mma_bf16(c, al[mt], bh[nt]);
                        mma_bf16(c, ah[mt], bl[nt]);
                    }
            }
        }
    }

    // epilogue: fragment (c0,c1)@(g,tig*2), (c2,c3)@(g+8,tig*2)
    int g = lane >> 2, tig = lane & 3;
    #pragma unroll
    for (int mt = 0; mt < 2; mt++)
        #pragma unroll
        for (int nt = 0; nt < 8; nt++) {
            float* c = acc[mt][nt];
            int m0 = row0 + m_base + mt * 16 + g;
            int col = n_base + nt * 8 + tig * 2;
            if (m0 < NN)
                *(float2*)&g_h[(size_t)m0 * DD + col] = make_float2(c[0], c[1]);
            if (m0 + 8 < NN)
                *(float2*)&g_h[(size_t)(m0 + 8) * DD + col] = make_float2(c[2], c[3]);
        }
}

// ---------------- SpMM: g_h2[d] = bias + selfw*h[d] + sum_e w[e]*h[col[e]] ----------------
// 8-edge unroll: 8 in-flight 128B gathers per warp; int2-packed edge stream.
__global__ void k_spmm(const float* __restrict__ bias) {
    int n    = (blockIdx.x * blockDim.x + threadIdx.x) >> 5;
    int lane = threadIdx.x & 31;
    if (n >= NN) return;
    const float4* h4 = (const float4*)g_h;
    float4 acc = ((const float4*)bias)[lane];
    float dn = g_dis[n];
    float sw = dn * dn;
    float4 hv = h4[(size_t)n * 32 + lane];
    acc.x = fmaf(sw, hv.x, acc.x);
    acc.y = fmaf(sw, hv.y, acc.y);
    acc.z = fmaf(sw, hv.z, acc.z);
    acc.w = fmaf(sw, hv.w, acc.w);
    int s = g_rowptr[n], e = g_rowptr[n + 1];
    int i = s;
    for (; i + 8 <= e; i += 8) {
        int2 e0 = g_edge[i],     e1 = g_edge[i + 1];
        int2 e2 = g_edge[i + 2], e3 = g_edge[i + 3];
        int2 e4 = g_edge[i + 4], e5 = g_edge[i + 5];
        int2 e6 = g_edge[i + 6], e7 = g_edge[i + 7];
        float4 v0 = h4[(size_t)e0.x * 32 + lane];
        float4 v1 = h4[(size_t)e1.x * 32 + lane];
        float4 v2 = h4[(size_t)e2.x * 32 + lane];
        float4 v3 = h4[(size_t)e3.x * 32 + lane];
        float4 v4 = h4[(size_t)e4.x * 32 + lane];
        float4 v5 = h4[(size_t)e5.x * 32 + lane];
        float4 v6 = h4[(size_t)e6.x * 32 + lane];
        float4 v7 = h4[(size_t)e7.x * 32 + lane];
        float w0 = __int_as_float(e0.y), w1 = __int_as_float(e1.y);
        float w2 = __int_as_float(e2.y), w3 = __int_as_float(e3.y);
        float w4 = __int_as_float(e4.y), w5 = __int_as_float(e5.y);
        float w6 = __int_as_float(e6.y), w7 = __int_as_float(e7.y);
        acc.x = fmaf(w0, v0.x, acc.x); acc.y = fmaf(w0, v0.y, acc.y);
        acc.z = fmaf(w0, v0.z, acc.z); acc.w = fmaf(w0, v0.w, acc.w);
        acc.x = fmaf(w1, v1.x, acc.x); acc.y = fmaf(w1, v1.y, acc.y);
        acc.z = fmaf(w1, v1.z, acc.z); acc.w = fmaf(w1, v1.w, acc.w);
        acc.x = fmaf(w2, v2.x, acc.x); acc.y = fmaf(w2, v2.y, acc.y);
        acc.z = fmaf(w2, v2.z, acc.z); acc.w = fmaf(w2, v2.w, acc.w);
        acc.x = fmaf(w3, v3.x, acc.x); acc.y = fmaf(w3, v3.y, acc.y);
        acc.z = fmaf(w3, v3.z, acc.z); acc.w = fmaf(w3, v3.w, acc.w);
        acc.x = fmaf(w4, v4.x, acc.x); acc.y = fmaf(w4, v4.y, acc.y);
        acc.z = fmaf(w4, v4.z, acc.z); acc.w = fmaf(w4, v4.w, acc.w);
        acc.x = fmaf(w5, v5.x, acc.x); acc.y = fmaf(w5, v5.y, acc.y);
        acc.z = fmaf(w5, v5.z, acc.z); acc.w = fmaf(w5, v5.w, acc.w);
        acc.x = fmaf(w6, v6.x, acc.x); acc.y = fmaf(w6, v6.y, acc.y);
        acc.z = fmaf(w6, v6.z, acc.z); acc.w = fmaf(w6, v6.w, acc.w);
        acc.x = fmaf(w7, v7.x, acc.x); acc.y = fmaf(w7, v7.y, acc.y);
        acc.z = fmaf(w7, v7.z, acc.z); acc.w = fmaf(w7, v7.w, acc.w);
    }
    for (; i < e; i++) {
        int2 e0 = g_edge[i];
        float w0 = __int_as_float(e0.y);
        float4 v0 = h4[(size_t)e0.x * 32 + lane];
        acc.x = fmaf(w0, v0.x, acc.x); acc.y = fmaf(w0, v0.y, acc.y);
        acc.z = fmaf(w0, v0.z, acc.z); acc.w = fmaf(w0, v0.w, acc.w);
    }
    ((float4*)g_h2)[(size_t)n * 32 + lane] = acc;
}

// ---------------- fused GraphNorm stats + apply: grid (GG, 4 feature-chunks) ------
// Pass 1: one-pass sum/sumsq over the graph's nodes -> am, wr (smem).
// Pass 2: normalize + ELU + residual, second h2 read is L2/L1-hot.
__global__ void __launch_bounds__(256) k_statsapply(const float* __restrict__ alpha,
                                                    const float* __restrict__ gw,
                                                    const float* __restrict__ gnb,
                                                    const float* __restrict__ xres,
                                                    float* __restrict__ out) {
    int g = blockIdx.x;
    int fc = blockIdx.y;
    int t = threadIdx.x;
    int f = fc * 32 + (t & 31), sl = t >> 5;
    int s = g_gptr[g], e = g_gptr[g + 1];
    int cnt = e - s;
    __shared__ float ssum[8][32], ssq[8][32];
    __shared__ float sam[32], swr[32], sb[32];
    float sum = 0.f, sq = 0.f;
    const float* p = g_h2 + (size_t)s * DD + f;
    #pragma unroll 4
    for (int n = sl; n < cnt; n += 8) {
        float v = p[(size_t)n * DD];
        sum += v; sq = fmaf(v, v, sq);
    }
    ssum[sl][t & 31] = sum; ssq[sl][t & 31] = sq;
    __syncthreads();
    if (t < 32) {
        float S = 0.f, Q = 0.f;
        #pragma unroll
        for (int i = 0; i < 8; i++) { S += ssum[i][t]; Q += ssq[i][t]; }
        float inv = (cnt > 0) ? 1.f / (float)cnt : 0.f;
        float mean = S * inv;
        float am = alpha[f] * mean;
        float var = fmaf(am, am, fmaf(-2.f * am, mean, Q * inv));
        sam[t] = am;
        swr[t] = gw[f] * rsqrtf(var + EPSV);
        sb[t]  = gnb[f];
    }
    __syncthreads();
    float am = sam[t & 31], wr = swr[t & 31], bb = sb[t & 31];
    const float* xr = xres + (size_t)s * DD + f;
    float* op = out + (size_t)s * DD + f;
    #pragma unroll 4
    for (int n = sl; n < cnt; n += 8) {
        float v = p[(size_t)n * DD];
        float z = (v - am) * wr + bb;
        op[(size_t)n * DD] = (z > 0.f ? z : expm1f(z)) + xr[(size_t)n * DD];
    }
}

// ---------------- global add pool: grid (GG, 4 chunks) x 256 ----------------
__global__ void __launch_bounds__(256) k_pool(const float* __restrict__ x) {
    int g = blockIdx.x;
    int fc = blockIdx.y;
    int t = threadIdx.x;
    int f = fc * 32 + (t & 31), sl = t >> 5;
    int s = g_gptr[g], e = g_gptr[g + 1];
    int cnt = e - s;
    __shared__ float ssum[8][32];
    float sum = 0.f;
    const float* p = x + (size_t)s * DD + f;
    #pragma unroll 4
    for (int n = sl; n < cnt; n += 8) sum += p[(size_t)n * DD];
    ssum[sl][t & 31] = sum;
    __syncthreads();
    if (t < 32) {
        float S = 0.f;
        #pragma unroll
        for (int i = 0; i < 8; i++) S += ssum[i][t];
        g_pool[g * DD + f] = S;
    }
}

// ---------------- MLP head (reads g_pool) ----------------
__global__ void k_mlp(const float* __restrict__ w1, const float* __restrict__ b1,
                      const float* __restrict__ bng, const float* __restrict__ bnb,
                      const float* __restrict__ bnm, const float* __restrict__ bnv,
                      const float* __restrict__ w2, const float* __restrict__ b2,
                      float* __restrict__ out) {
    int g = blockIdx.x, d = threadIdx.x;
    __shared__ float p[DD], z1[DD];
    p[d] = g_pool[g * DD + d];
    __syncthreads();
    float z = b1[d];
    #pragma unroll 4
    for (int k = 0; k < DD; k++) z = fmaf(p[k], w1[k * DD + d], z);
    z = bng[d] * (z - bnm[d]) * rsqrtf(bnv[d] + EPSV) + bnb[d];
    z = z > 0.f ? z : 0.f;
    z1[d] = z;
    __syncthreads();
    if (d < NCLS) {
        float o = b2[d];
        #pragma unroll 4
        for (int k = 0; k < DD; k++) o = fmaf(z1[k], w2[k * NCLS + d], o);
        out[(size_t)NN * DD + g * NCLS + d] = o;
    }
}

// ---------------- launch ----------------
extern "C" void kernel_launch(void* const* d_in, const int* in_sizes, int n_in,
                              void* d_out, int out_size) {
    const float* x0     = (const float*)d_in[0];
    const void*  ei     = d_in[1];
    const void*  batch  = d_in[2];
    const float* conv_w = (const float*)d_in[3];
    const float* conv_b = (const float*)d_in[4];
    const float* gn_w   = (const float*)d_in[5];
    const float* gn_b   = (const float*)d_in[6];
    const float* gn_ms  = (const float*)d_in[7];
    const float* w1     = (const float*)d_in[8];
    const float* b1     = (const float*)d_in[9];
    const float* bng    = (const float*)d_in[10];
    const float* bnb    = (const float*)d_in[11];
    const float* bnm    = (const float*)d_in[12];
    const float* bnv    = (const float*)d_in[13];
    const float* w2     = (const float*)d_in[14];
    const float* b2     = (const float*)d_in[15];
    float* out = (float*)d_out;

    const int GEMM_GRID = (NN + 127) / 128;

    // layer-0 GEMM at launch slot 4 so ncu profiles it.
    k_detect<<<1, 256>>>((const int*)ei);
    k_init<<<256, 256>>>();
    k_wconv<<<64, 256>>>(conv_w);
    k_gemm_mma<<<GEMM_GRID, 256>>>(x0);
    k_hist<<<(EE + 255) / 256, 256>>>(ei);
    k_cvt_batch<<<(NN + 255) / 256, 256>>>(batch);
    k_scan1<<<NB, 256>>>();
    k_scan2<<<1, 32>>>();
    k_scan3<<<NB, 256>>>();
    k_scatter<<<(EE + 255) / 256, 256>>>(ei);

    const float* xin = x0;
    for (int l = 0; l < LL; l++) {
        if (l > 0) {
            k_wconv<<<64, 256>>>(conv_w + (size_t)l * DD * DD);
            k_gemm_mma<<<GEMM_GRID, 256>>>(xin);
        }
        k_spmm<<<(NN + 7) / 8, 256>>>(conv_b + (size_t)l * DD);
        k_statsapply<<<dim3(GG, 4), 256>>>(gn_ms + (size_t)l * DD, gn_w + (size_t)l * DD,
                                           gn_b + (size_t)l * DD, xin, out);
        xin = out;
    }
    k_pool<<<dim3(GG, 4), 256>>>(out);
    k_mlp<<<GG, DD>>>(w1, b1, bng, bnb, bnm, bnv, w2, b2, out);
}

// round 16
// speedup vs baseline: 1.2230x; 1.2230x over previous
#include <cuda_runtime.h>
#include <cuda_bf16.h>
#include <math.h>
#include <stdint.h>

#define NN   100000
#define EE   1600000
#define DD   128
#define GG   128
#define LL   4
#define NCLS 10
#define EPSV 1e-5f
#define NB   391          // ceil(NN/256) scan blocks

// ---------------- scratch (static device globals; no allocation) ----------------
static __device__ __align__(16) float g_h [(size_t)NN * DD];   // GEMM output (gather source)
static __device__ __align__(16) float g_h2[(size_t)NN * DD];   // SpMM output
static __device__ __align__(16) float g_am[GG * DD];           // alpha * mean
static __device__ __align__(16) float g_wr[GG * DD];           // gn_weight * rstd
static __device__ __align__(16) float g_pool[GG * DD];         // pooled sums
static __device__ __align__(16) float g_dis[NN];
static __device__ __align__(8)  int2  g_edge[EE];              // {col, weight-as-int}
static __device__ __align__(16) __nv_bfloat16 g_wth[DD * DD];  // W^T hi  [n][k]
static __device__ __align__(16) __nv_bfloat16 g_wtl[DD * DD];  // W^T lo  [n][k]
static __device__ int   g_batch[NN];
static __device__ int   g_cnt[NN];
static __device__ int   g_fill[NN];
static __device__ int   g_rowptr[NN + 1];
static __device__ int   g_gptr[GG + 1];
static __device__ int   g_part[NB];
static __device__ int   g_i64;

// ---------------- mma helpers (standard PTX, sm_80+, fine on compute_103) --------
__device__ __forceinline__ void ldsm4(uint32_t r[4], uint32_t addr) {
    asm volatile("ldmatrix.sync.aligned.m8n8.x4.shared.b16 {%0,%1,%2,%3}, [%4];"
                 : "=r"(r[0]), "=r"(r[1]), "=r"(r[2]), "=r"(r[3]) : "r"(addr));
}
__device__ __forceinline__ void mma_bf16(float c[4], const uint32_t a[4], const uint32_t b[2]) {
    asm volatile("mma.sync.aligned.m16n8k16.row.col.f32.bf16.bf16.f32 "
                 "{%0,%1,%2,%3}, {%4,%5,%6,%7}, {%8,%9}, {%0,%1,%2,%3};"
                 : "+f"(c[0]), "+f"(c[1]), "+f"(c[2]), "+f"(c[3])
                 : "r"(a[0]), "r"(a[1]), "r"(a[2]), "r"(a[3]), "r"(b[0]), "r"(b[1]));
}
__device__ __forceinline__ uint32_t smem_u32(const void* p) {
    return (uint32_t)__cvta_generic_to_shared(p);
}
__device__ __forceinline__ uint32_t pack2(float f0, float f1) {
    __nv_bfloat16 h0 = __float2bfloat16(f0), h1 = __float2bfloat16(f1);
    return ((uint32_t)__bfloat16_as_ushort(h1) << 16) | __bfloat16_as_ushort(h0);
}
__device__ __forceinline__ uint32_t pack2lo(float f0, float f1) {
    __nv_bfloat16 h0 = __float2bfloat16(f0), h1 = __float2bfloat16(f1);
    float l0 = f0 - __bfloat162float(h0), l1 = f1 - __bfloat162float(h1);
    __nv_bfloat16 g0 = __float2bfloat16(l0), g1 = __float2bfloat16(l1);
    return ((uint32_t)__bfloat16_as_ushort(g1) << 16) | __bfloat16_as_ushort(g0);
}

// ---------------- dtype detection: int64 vs int32 index buffers ----------------
__global__ void k_detect(const int* __restrict__ eiw) {
    __shared__ int bad;
    if (threadIdx.x == 0) bad = 0;
    __syncthreads();
    for (int i = threadIdx.x; i < 2048; i += blockDim.x)
        if (eiw[2 * i + 1] != 0) bad = 1;
    __syncthreads();
    if (threadIdx.x == 0) g_i64 = bad ? 0 : 1;
}

// ---------------- preprocessing ----------------
__global__ void k_init() {
    int i = blockIdx.x * blockDim.x + threadIdx.x;
    int stride = gridDim.x * blockDim.x;
    for (int n = i; n < NN; n += stride) { g_cnt[n] = 0; g_fill[n] = 0; }
}

__global__ void k_hist(const void* __restrict__ ei) {
    int e = blockIdx.x * blockDim.x + threadIdx.x;
    if (e >= EE) return;
    int d = g_i64 ? (int)((const long long*)ei)[EE + e] : ((const int*)ei)[EE + e];
    if ((unsigned)d >= NN) d = 0;
    atomicAdd(&g_cnt[d], 1);
}

// batch is sorted: derive g_gptr from boundaries, no atomics.
__global__ void k_cvt_batch(const void* __restrict__ batch) {
    int n = blockIdx.x * blockDim.x + threadIdx.x;
    if (n >= NN) return;
    int b, bp = -1;
    if (g_i64) {
        const long long* p = (const long long*)batch;
        b = (int)p[n];
        if (n > 0) bp = (int)p[n - 1];
    } else {
        const int* p = (const int*)batch;
        b = p[n];
        if (n > 0) bp = p[n - 1];
    }
    if ((unsigned)b >= GG) b = 0;
    if (n > 0 && (unsigned)bp >= GG) bp = 0;
    g_batch[n] = b;
    if (b != bp)
        for (int g = bp + 1; g <= b; g++) g_gptr[g] = n;
    if (n == NN - 1)
        for (int g = b + 1; g <= GG; g++) g_gptr[g] = NN;
}

// ---------------- parallel 3-step scan (also computes dis = rsqrt(deg)) -----------
__global__ void k_scan1() {
    __shared__ int sh[256];
    int b = blockIdx.x, t = threadIdx.x;
    int i = b * 256 + t;
    int v = (i < NN) ? g_cnt[i] : 0;
    if (i < NN) g_dis[i] = rsqrtf((float)(v + 1));
    sh[t] = v;
    __syncthreads();
    for (int o = 128; o > 0; o >>= 1) {
        if (t < o) sh[t] += sh[t + o];
        __syncthreads();
    }
    if (t == 0) g_part[b] = sh[0];
}
__global__ void k_scan2() {
    if (threadIdx.x == 0) {
        int r = 0;
        for (int i = 0; i < NB; i++) { int v = g_part[i]; g_part[i] = r; r += v; }
        g_rowptr[NN] = EE;
    }
}
__global__ void k_scan3() {
    __shared__ int sh[256];
    int b = blockIdx.x, t = threadIdx.x;
    int i = b * 256 + t;
    int v = (i < NN) ? g_cnt[i] : 0;
    sh[t] = v;
    __syncthreads();
    for (int o = 1; o < 256; o <<= 1) {
        int x = (t >= o) ? sh[t - o] : 0;
        __syncthreads();
        sh[t] += x;
        __syncthreads();
    }
    if (i < NN) g_rowptr[i] = g_part[b] + sh[t] - v;
}

__global__ void k_scatter(const void* __restrict__ ei) {
    int e = blockIdx.x * blockDim.x + threadIdx.x;
    if (e >= EE) return;
    int s, d;
    if (g_i64) {
        const long long* p = (const long long*)ei;
        s = (int)p[e]; d = (int)p[EE + e];
    } else {
        const int* p = (const int*)ei;
        s = p[e]; d = p[EE + e];
    }
    if ((unsigned)s >= NN) s = 0;
    if ((unsigned)d >= NN) d = 0;
    int pos = g_rowptr[d] + atomicAdd(&g_fill[d], 1);
    g_edge[pos] = make_int2(s, __float_as_int(g_dis[s] * g_dis[d]));
}

// ---------------- W -> bf16 hi/lo transposed images [n][k] ----------------
__global__ void k_wconv(const float* __restrict__ W) {
    int i = blockIdx.x * 256 + threadIdx.x;
    if (i >= DD * DD) return;
    int n = i >> 7, k = i & 127;
    float w = W[k * DD + n];
    __nv_bfloat16 h = __float2bfloat16(w);
    __nv_bfloat16 l = __float2bfloat16(w - __bfloat162float(h));
    g_wth[i] = h;    // coalesced along k
    g_wtl[i] = l;
}

// ---------------- GEMM: g_h = X @ W via mma.sync bf16 hi/lo 3-split ----------------
// 256 thr (8 warps: 4m x 2n), 128 rows x 128 cols per block, K chunked x32.
// launch_bounds(.,2): cap regs at 128 -> 2 CTAs/SM for latency hiding.
#define LDAB 40   // bf16 row stride (80 B): conflict-free ldmatrix phases
__global__ void __launch_bounds__(256, 2) k_gemm_mma(const float* __restrict__ X) {
    __shared__ __align__(16) __nv_bfloat16 sAh[128][LDAB];
    __shared__ __align__(16) __nv_bfloat16 sAl[128][LDAB];
    __shared__ __align__(16) __nv_bfloat16 sBh[128][LDAB];
    __shared__ __align__(16) __nv_bfloat16 sBl[128][LDAB];
    int tid = threadIdx.x, lane = tid & 31, wid = tid >> 5;
    int row0 = blockIdx.x * 128;
    int m_base = (wid & 3) * 32;
    int n_base = (wid >> 2) * 64;

    float acc[2][8][4];
    #pragma unroll
    for (int i = 0; i < 2; i++)
        #pragma unroll
        for (int j = 0; j < 8; j++)
            #pragma unroll
            for (int q = 0; q < 4; q++) acc[i][j][q] = 0.f;

    // per-lane ldmatrix base addresses
    int li = lane & 7, mi = lane >> 3;
    uint32_t aAh = smem_u32(&sAh[m_base + (mi & 1) * 8 + li][(mi >> 1) * 8]);
    uint32_t aAl = smem_u32(&sAl[m_base + (mi & 1) * 8 + li][(mi >> 1) * 8]);
    uint32_t aBh = smem_u32(&sBh[n_base + (mi >> 1) * 8 + li][(mi & 1) * 8]);
    uint32_t aBl = smem_u32(&sBl[n_base + (mi >> 1) * 8 + li][(mi & 1) * 8]);

    const float4* X4 = (const float4*)X;
    for (int kc = 0; kc < 4; kc++) {
        __syncthreads();
        // A: load 128x32 fp32 chunk, convert to bf16 hi/lo
        #pragma unroll
        for (int it = 0; it < 4; it++) {
            int t4 = tid + it * 256;            // 1024 float4
            int r = t4 >> 3, c4 = t4 & 7;
            int m = row0 + r;
            float4 v = make_float4(0.f, 0.f, 0.f, 0.f);
            if (m < NN) v = X4[(size_t)m * 32 + kc * 8 + c4];
            uint2 hi, lo;
            hi.x = pack2(v.x, v.y);  hi.y = pack2(v.z, v.w);
            lo.x = pack2lo(v.x, v.y); lo.y = pack2lo(v.z, v.w);
            *(uint2*)((char*)&sAh[0][0] + r * (LDAB * 2) + c4 * 8) = hi;
            *(uint2*)((char*)&sAl[0][0] + r * (LDAB * 2) + c4 * 8) = lo;
        }
        // B: linear copy of pre-transposed images
        #pragma unroll
        for (int it = 0; it < 2; it++) {
            int t2 = tid + it * 256;            // 512 uint4
            int n = t2 >> 2, q = t2 & 3;
            *(uint4*)((char*)&sBh[0][0] + n * (LDAB * 2) + q * 16) =
                ((const uint4*)g_wth)[n * 16 + kc * 4 + q];
            *(uint4*)((char*)&sBl[0][0] + n * (LDAB * 2) + q * 16) =
                ((const uint4*)g_wtl)[n * 16 + kc * 4 + q];
        }
        __syncthreads();

        #pragma unroll
        for (int ks = 0; ks < 2; ks++) {
            int k0b = ks * 32;                  // bytes (16 bf16)
            uint32_t ah[2][4], al[2][4];
            ldsm4(ah[0], aAh + k0b);
            ldsm4(ah[1], aAh + 16 * (LDAB * 2) + k0b);
            ldsm4(al[0], aAl + k0b);
            ldsm4(al[1], aAl + 16 * (LDAB * 2) + k0b);
            #pragma unroll
            for (int grp = 0; grp < 2; grp++) {
                uint32_t bh[4][2], bl[4][2];
                uint32_t off = grp * 32 * (LDAB * 2) + k0b;
                ldsm4(&bh[0][0], aBh + off);
                ldsm4(&bh[2][0], aBh + off + 16 * (LDAB * 2));
                ldsm4(&bl[0][0], aBl + off);
                ldsm4(&bl[2][0], aBl + off + 16 * (LDAB * 2));
                #pragma unroll
                for (int mt = 0; mt < 2; mt++)
                    #pragma unroll
                    for (int nt = 0; nt < 4; nt++) {
                        float* c = acc[mt][grp * 4 + nt];
                        mma_bf16(c, ah[mt], bh[nt]);
                        mma_bf16(c, al[mt], bh[nt]);
                        mma_bf16(c, ah[mt], bl[nt]);
                    }
            }
        }
    }

    // epilogue: fragment (c0,c1)@(g,tig*2), (c2,c3)@(g+8,tig*2)
    int g = lane >> 2, tig = lane & 3;
    #pragma unroll
    for (int mt = 0; mt < 2; mt++)
        #pragma unroll
        for (int nt = 0; nt < 8; nt++) {
            float* c = acc[mt][nt];
            int m0 = row0 + m_base + mt * 16 + g;
            int col = n_base + nt * 8 + tig * 2;
            if (m0 < NN)
                *(float2*)&g_h[(size_t)m0 * DD + col] = make_float2(c[0], c[1]);
            if (m0 + 8 < NN)
                *(float2*)&g_h[(size_t)(m0 + 8) * DD + col] = make_float2(c[2], c[3]);
        }
}

// ---------------- SpMM: g_h2[d] = bias + selfw*h[d] + sum_e w[e]*h[col[e]] ----------------
// 8-edge unroll: 8 in-flight 128B gathers per warp; int2-packed edge stream.
__global__ void k_spmm(const float* __restrict__ bias) {
    int n    = (blockIdx.x * blockDim.x + threadIdx.x) >> 5;
    int lane = threadIdx.x & 31;
    if (n >= NN) return;
    const float4* h4 = (const float4*)g_h;
    float4 acc = ((const float4*)bias)[lane];
    float dn = g_dis[n];
    float sw = dn * dn;
    float4 hv = h4[(size_t)n * 32 + lane];
    acc.x = fmaf(sw, hv.x, acc.x);
    acc.y = fmaf(sw, hv.y, acc.y);
    acc.z = fmaf(sw, hv.z, acc.z);
    acc.w = fmaf(sw, hv.w, acc.w);
    int s = g_rowptr[n], e = g_rowptr[n + 1];
    int i = s;
    for (; i + 8 <= e; i += 8) {
        int2 e0 = g_edge[i],     e1 = g_edge[i + 1];
        int2 e2 = g_edge[i + 2], e3 = g_edge[i + 3];
        int2 e4 = g_edge[i + 4], e5 = g_edge[i + 5];
        int2 e6 = g_edge[i + 6], e7 = g_edge[i + 7];
        float4 v0 = h4[(size_t)e0.x * 32 + lane];
        float4 v1 = h4[(size_t)e1.x * 32 + lane];
        float4 v2 = h4[(size_t)e2.x * 32 + lane];
        float4 v3 = h4[(size_t)e3.x * 32 + lane];
        float4 v4 = h4[(size_t)e4.x * 32 + lane];
        float4 v5 = h4[(size_t)e5.x * 32 + lane];
        float4 v6 = h4[(size_t)e6.x * 32 + lane];
        float4 v7 = h4[(size_t)e7.x * 32 + lane];
        float w0 = __int_as_float(e0.y), w1 = __int_as_float(e1.y);
        float w2 = __int_as_float(e2.y), w3 = __int_as_float(e3.y);
        float w4 = __int_as_float(e4.y), w5 = __int_as_float(e5.y);
        float w6 = __int_as_float(e6.y), w7 = __int_as_float(e7.y);
        acc.x = fmaf(w0, v0.x, acc.x); acc.y = fmaf(w0, v0.y, acc.y);
        acc.z = fmaf(w0, v0.z, acc.z); acc.w = fmaf(w0, v0.w, acc.w);
        acc.x = fmaf(w1, v1.x, acc.x); acc.y = fmaf(w1, v1.y, acc.y);
        acc.z = fmaf(w1, v1.z, acc.z); acc.w = fmaf(w1, v1.w, acc.w);
        acc.x = fmaf(w2, v2.x, acc.x); acc.y = fmaf(w2, v2.y, acc.y);
        acc.z = fmaf(w2, v2.z, acc.z); acc.w = fmaf(w2, v2.w, acc.w);
        acc.x = fmaf(w3, v3.x, acc.x); acc.y = fmaf(w3, v3.y, acc.y);
        acc.z = fmaf(w3, v3.z, acc.z); acc.w = fmaf(w3, v3.w, acc.w);
        acc.x = fmaf(w4, v4.x, acc.x); acc.y = fmaf(w4, v4.y, acc.y);
        acc.z = fmaf(w4, v4.z, acc.z); acc.w = fmaf(w4, v4.w, acc.w);
        acc.x = fmaf(w5, v5.x, acc.x); acc.y = fmaf(w5, v5.y, acc.y);
        acc.z = fmaf(w5, v5.z, acc.z); acc.w = fmaf(w5, v5.w, acc.w);
        acc.x = fmaf(w6, v6.x, acc.x); acc.y = fmaf(w6, v6.y, acc.y);
        acc.z = fmaf(w6, v6.z, acc.z); acc.w = fmaf(w6, v6.w, acc.w);
        acc.x = fmaf(w7, v7.x, acc.x); acc.y = fmaf(w7, v7.y, acc.y);
        acc.z = fmaf(w7, v7.z, acc.z); acc.w = fmaf(w7, v7.w, acc.w);
    }
    for (; i < e; i++) {
        int2 e0 = g_edge[i];
        float w0 = __int_as_float(e0.y);
        float4 v0 = h4[(size_t)e0.x * 32 + lane];
        acc.x = fmaf(w0, v0.x, acc.x); acc.y = fmaf(w0, v0.y, acc.y);
        acc.z = fmaf(w0, v0.z, acc.z); acc.w = fmaf(w0, v0.w, acc.w);
    }
    ((float4*)g_h2)[(size_t)n * 32 + lane] = acc;
}

// ---------------- GraphNorm stats: one pass, grid (GG, 4 feature-chunks) ----------------
__global__ void __launch_bounds__(256) k_stats(const float* __restrict__ alpha,
                                               const float* __restrict__ gw) {
    int g = blockIdx.x;
    int fc = blockIdx.y;
    int t = threadIdx.x;
    int f = fc * 32 + (t & 31), sl = t >> 5;
    int s = g_gptr[g], e = g_gptr[g + 1];
    int cnt = e - s;
    __shared__ float ssum[8][32], ssq[8][32];
    float sum = 0.f, sq = 0.f;
    const float* p = g_h2 + (size_t)s * DD + f;
    #pragma unroll 4
    for (int n = sl; n < cnt; n += 8) {
        float v = p[(size_t)n * DD];
        sum += v; sq = fmaf(v, v, sq);
    }
    ssum[sl][t & 31] = sum; ssq[sl][t & 31] = sq;
    __syncthreads();
    if (t < 32) {
        if (cnt <= 0) { g_am[g * DD + f] = 0.f; g_wr[g * DD + f] = 0.f; return; }
        float S = 0.f, Q = 0.f;
        #pragma unroll
        for (int i = 0; i < 8; i++) { S += ssum[i][t]; Q += ssq[i][t]; }
        float inv = 1.f / (float)cnt;
        float mean = S * inv;
        float am = alpha[f] * mean;
        float var = fmaf(am, am, fmaf(-2.f * am, mean, Q * inv));
        g_am[g * DD + f] = am;
        g_wr[g * DD + f] = gw[f] * rsqrtf(var + EPSV);
    }
}

// ---------------- normalize + ELU + residual -> out (x) ----------------
__global__ void k_apply(const float* __restrict__ xres, const float* __restrict__ gnb,
                        float* __restrict__ out) {
    int t = blockIdx.x * blockDim.x + threadIdx.x;
    if (t >= NN * 32) return;
    int n = t >> 5, q = t & 31;
    int g = g_batch[n];
    float4 h = ((const float4*)g_h2)[t];
    float4 a = ((const float4*)g_am)[g * 32 + q];
    float4 w = ((const float4*)g_wr)[g * 32 + q];
    float4 b = ((const float4*)gnb)[q];
    float4 r = ((const float4*)xres)[t];
    float4 o;
    float v;
    v = (h.x - a.x) * w.x + b.x; o.x = (v > 0.f ? v : expm1f(v)) + r.x;
    v = (h.y - a.y) * w.y + b.y; o.y = (v > 0.f ? v : expm1f(v)) + r.y;
    v = (h.z - a.z) * w.z + b.z; o.z = (v > 0.f ? v : expm1f(v)) + r.z;
    v = (h.w - a.w) * w.w + b.w; o.w = (v > 0.f ? v : expm1f(v)) + r.w;
    ((float4*)out)[t] = o;
}

// ---------------- global add pool: grid (GG, 4 chunks) x 256 ----------------
__global__ void __launch_bounds__(256) k_pool(const float* __restrict__ x) {
    int g = blockIdx.x;
    int fc = blockIdx.y;
    int t = threadIdx.x;
    int f = fc * 32 + (t & 31), sl = t >> 5;
    int s = g_gptr[g], e = g_gptr[g + 1];
    int cnt = e - s;
    __shared__ float ssum[8][32];
    float sum = 0.f;
    const float* p = x + (size_t)s * DD + f;
    #pragma unroll 4
    for (int n = sl; n < cnt; n += 8) sum += p[(size_t)n * DD];
    ssum[sl][t & 31] = sum;
    __syncthreads();
    if (t < 32) {
        float S = 0.f;
        #pragma unroll
        for (int i = 0; i < 8; i++) S += ssum[i][t];
        g_pool[g * DD + f] = S;
    }
}

// ---------------- MLP head (reads g_pool) ----------------
__global__ void k_mlp(const float* __restrict__ w1, const float* __restrict__ b1,
                      const float* __restrict__ bng, const float* __restrict__ bnb,
                      const float* __restrict__ bnm, const float* __restrict__ bnv,
                      const float* __restrict__ w2, const float* __restrict__ b2,
                      float* __restrict__ out) {
    int g = blockIdx.x, d = threadIdx.x;
    __shared__ float p[DD], z1[DD];
    p[d] = g_pool[g * DD + d];
    __syncthreads();
    float z = b1[d];
    #pragma unroll 4
    for (int k = 0; k < DD; k++) z = fmaf(p[k], w1[k * DD + d], z);
    z = bng[d] * (z - bnm[d]) * rsqrtf(bnv[d] + EPSV) + bnb[d];
    z = z > 0.f ? z : 0.f;
    z1[d] = z;
    __syncthreads();
    if (d < NCLS) {
        float o = b2[d];
        #pragma unroll 4
        for (int k = 0; k < DD; k++) o = fmaf(z1[k], w2[k * NCLS + d], o);
        out[(size_t)NN * DD + g * NCLS + d] = o;
    }
}

// ---------------- launch ----------------
extern "C" void kernel_launch(void* const* d_in, const int* in_sizes, int n_in,
                              void* d_out, int out_size) {
    const float* x0     = (const float*)d_in[0];
    const void*  ei     = d_in[1];
    const void*  batch  = d_in[2];
    const float* conv_w = (const float*)d_in[3];
    const float* conv_b = (const float*)d_in[4];
    const float* gn_w   = (const float*)d_in[5];
    const float* gn_b   = (const float*)d_in[6];
    const float* gn_ms  = (const float*)d_in[7];
    const float* w1     = (const float*)d_in[8];
    const float* b1     = (const float*)d_in[9];
    const float* bng    = (const float*)d_in[10];
    const float* bnb    = (const float*)d_in[11];
    const float* bnm    = (const float*)d_in[12];
    const float* bnv    = (const float*)d_in[13];
    const float* w2     = (const float*)d_in[14];
    const float* b2     = (const float*)d_in[15];
    float* out = (float*)d_out;

    const int GEMM_GRID = (NN + 127) / 128;

    // layer-0 GEMM at launch slot 4 so ncu profiles it.
    k_detect<<<1, 256>>>((const int*)ei);
    k_init<<<256, 256>>>();
    k_wconv<<<64, 256>>>(conv_w);
    k_gemm_mma<<<GEMM_GRID, 256>>>(x0);
    k_hist<<<(EE + 255) / 256, 256>>>(ei);
    k_cvt_batch<<<(NN + 255) / 256, 256>>>(batch);
    k_scan1<<<NB, 256>>>();
    k_scan2<<<1, 32>>>();
    k_scan3<<<NB, 256>>>();
    k_scatter<<<(EE + 255) / 256, 256>>>(ei);

    const float* xin = x0;
    for (int l = 0; l < LL; l++) {
        if (l > 0) {
            k_wconv<<<64, 256>>>(conv_w + (size_t)l * DD * DD);
            k_gemm_mma<<<GEMM_GRID, 256>>>(xin);
        }
        k_spmm<<<(NN + 7) / 8, 256>>>(conv_b + (size_t)l * DD);
        k_stats<<<dim3(GG, 4), 256>>>(gn_ms + (size_t)l * DD, gn_w + (size_t)l * DD);
        k_apply<<<(NN * 32 + 255) / 256, 256>>>(xin, gn_b + (size_t)l * DD, out);
        xin = out;
    }
    k_pool<<<dim3(GG, 4), 256>>>(out);
    k_mlp<<<GG, DD>>>(w1, b1, bng, bnb, bnm, bnv, w2, b2, out);
}

// round 17
// speedup vs baseline: 1.2903x; 1.0550x over previous
#include <cuda_runtime.h>
#include <cuda_bf16.h>
#include <math.h>
#include <stdint.h>

#define NN   100000
#define EE   1600000
#define DD   128
#define GG   128
#define LL   4
#define NCLS 10
#define EPSV 1e-5f
#define NB   391          // ceil(NN/256) scan blocks

// ---------------- scratch (static device globals; no allocation) ----------------
static __device__ __align__(16) float g_h [(size_t)NN * DD];   // GEMM output (gather source)
static __device__ __align__(16) float g_h2[(size_t)NN * DD];   // SpMM output
static __device__ __align__(16) float g_am[GG * DD];           // alpha * mean
static __device__ __align__(16) float g_wr[GG * DD];           // gn_weight * rstd
static __device__ __align__(16) float g_pool[GG * DD];         // pooled sums
static __device__ __align__(16) float g_we[EE];
static __device__ __align__(16) float g_dis[NN];
static __device__ __align__(16) __nv_bfloat16 g_wth[LL * DD * DD];  // W^T hi [l][n][k]
static __device__ __align__(16) __nv_bfloat16 g_wtl[LL * DD * DD];  // W^T lo [l][n][k]
static __device__ int   g_col[EE];
static __device__ int   g_batch[NN];
static __device__ int   g_cnt[NN];
static __device__ int   g_fill[NN];
static __device__ int   g_rowptr[NN + 1];
static __device__ int   g_gptr[GG + 1];
static __device__ int   g_part[NB];
static __device__ int   g_i64;

// ---------------- mma helpers (standard PTX, sm_80+, fine on compute_103) --------
__device__ __forceinline__ void ldsm4(uint32_t r[4], uint32_t addr) {
    asm volatile("ldmatrix.sync.aligned.m8n8.x4.shared.b16 {%0,%1,%2,%3}, [%4];"
                 : "=r"(r[0]), "=r"(r[1]), "=r"(r[2]), "=r"(r[3]) : "r"(addr));
}
__device__ __forceinline__ void mma_bf16(float c[4], const uint32_t a[4], const uint32_t b[2]) {
    asm volatile("mma.sync.aligned.m16n8k16.row.col.f32.bf16.bf16.f32 "
                 "{%0,%1,%2,%3}, {%4,%5,%6,%7}, {%8,%9}, {%0,%1,%2,%3};"
                 : "+f"(c[0]), "+f"(c[1]), "+f"(c[2]), "+f"(c[3])
                 : "r"(a[0]), "r"(a[1]), "r"(a[2]), "r"(a[3]), "r"(b[0]), "r"(b[1]));
}
__device__ __forceinline__ uint32_t smem_u32(const void* p) {
    return (uint32_t)__cvta_generic_to_shared(p);
}
__device__ __forceinline__ uint32_t pack2(float f0, float f1) {
    __nv_bfloat16 h0 = __float2bfloat16(f0), h1 = __float2bfloat16(f1);
    return ((uint32_t)__bfloat16_as_ushort(h1) << 16) | __bfloat16_as_ushort(h0);
}
__device__ __forceinline__ uint32_t pack2lo(float f0, float f1) {
    __nv_bfloat16 h0 = __float2bfloat16(f0), h1 = __float2bfloat16(f1);
    float l0 = f0 - __bfloat162float(h0), l1 = f1 - __bfloat162float(h1);
    __nv_bfloat16 g0 = __float2bfloat16(l0), g1 = __float2bfloat16(l1);
    return ((uint32_t)__bfloat16_as_ushort(g1) << 16) | __bfloat16_as_ushort(g0);
}

// ---------------- setup: dtype detect (block 0) + counter zeroing (all blocks) ----
__global__ void k_setup(const int* __restrict__ eiw) {
    int i = blockIdx.x * blockDim.x + threadIdx.x;
    int stride = gridDim.x * blockDim.x;
    for (int n = i; n < NN; n += stride) { g_cnt[n] = 0; g_fill[n] = 0; }
    if (blockIdx.x == 0) {
        __shared__ int bad;
        if (threadIdx.x == 0) bad = 0;
        __syncthreads();
        for (int j = threadIdx.x; j < 2048; j += blockDim.x)
            if (eiw[2 * j + 1] != 0) bad = 1;
        __syncthreads();
        if (threadIdx.x == 0) g_i64 = bad ? 0 : 1;
    }
}

__global__ void k_hist(const void* __restrict__ ei) {
    int e = blockIdx.x * blockDim.x + threadIdx.x;
    if (e >= EE) return;
    int d = g_i64 ? (int)((const long long*)ei)[EE + e] : ((const int*)ei)[EE + e];
    if ((unsigned)d >= NN) d = 0;
    atomicAdd(&g_cnt[d], 1);
}

// batch is sorted: derive g_gptr from boundaries, no atomics.
__global__ void k_cvt_batch(const void* __restrict__ batch) {
    int n = blockIdx.x * blockDim.x + threadIdx.x;
    if (n >= NN) return;
    int b, bp = -1;
    if (g_i64) {
        const long long* p = (const long long*)batch;
        b = (int)p[n];
        if (n > 0) bp = (int)p[n - 1];
    } else {
        const int* p = (const int*)batch;
        b = p[n];
        if (n > 0) bp = p[n - 1];
    }
    if ((unsigned)b >= GG) b = 0;
    if (n > 0 && (unsigned)bp >= GG) bp = 0;
    g_batch[n] = b;
    if (b != bp)
        for (int g = bp + 1; g <= b; g++) g_gptr[g] = n;
    if (n == NN - 1)
        for (int g = b + 1; g <= GG; g++) g_gptr[g] = NN;
}

// ---------------- parallel 3-step scan (also computes dis = rsqrt(deg)) -----------
__global__ void k_scan1() {
    __shared__ int sh[256];
    int b = blockIdx.x, t = threadIdx.x;
    int i = b * 256 + t;
    int v = (i < NN) ? g_cnt[i] : 0;
    if (i < NN) g_dis[i] = rsqrtf((float)(v + 1));
    sh[t] = v;
    __syncthreads();
    for (int o = 128; o > 0; o >>= 1) {
        if (t < o) sh[t] += sh[t + o];
        __syncthreads();
    }
    if (t == 0) g_part[b] = sh[0];
}
__global__ void k_scan2() {
    if (threadIdx.x == 0) {
        int r = 0;
        for (int i = 0; i < NB; i++) { int v = g_part[i]; g_part[i] = r; r += v; }
        g_rowptr[NN] = EE;
    }
}
__global__ void k_scan3() {
    __shared__ int sh[256];
    int b = blockIdx.x, t = threadIdx.x;
    int i = b * 256 + t;
    int v = (i < NN) ? g_cnt[i] : 0;
    sh[t] = v;
    __syncthreads();
    for (int o = 1; o < 256; o <<= 1) {
        int x = (t >= o) ? sh[t - o] : 0;
        __syncthreads();
        sh[t] += x;
        __syncthreads();
    }
    if (i < NN) g_rowptr[i] = g_part[b] + sh[t] - v;
}

__global__ void k_scatter(const void* __restrict__ ei) {
    int e = blockIdx.x * blockDim.x + threadIdx.x;
    if (e >= EE) return;
    int s, d;
    if (g_i64) {
        const long long* p = (const long long*)ei;
        s = (int)p[e]; d = (int)p[EE + e];
    } else {
        const int* p = (const int*)ei;
        s = p[e]; d = p[EE + e];
    }
    if ((unsigned)s >= NN) s = 0;
    if ((unsigned)d >= NN) d = 0;
    int pos = g_rowptr[d] + atomicAdd(&g_fill[d], 1);
    g_col[pos] = s;
    g_we[pos]  = g_dis[s] * g_dis[d];
}

// ---------------- all-layer W -> bf16 hi/lo transposed images [l][n][k] -----------
__global__ void k_wconv_all(const float* __restrict__ W) {
    int l = blockIdx.y;
    int i = blockIdx.x * 256 + threadIdx.x;
    if (i >= DD * DD) return;
    int n = i >> 7, k = i & 127;
    float w = W[(size_t)l * DD * DD + k * DD + n];
    __nv_bfloat16 h = __float2bfloat16(w);
    __nv_bfloat16 lo = __float2bfloat16(w - __bfloat162float(h));
    g_wth[l * DD * DD + i] = h;    // coalesced along k
    g_wtl[l * DD * DD + i] = lo;
}

// ---------------- GEMM: g_h = X @ W via mma.sync bf16 hi/lo 3-split ----------------
// 256 thr (8 warps: 4m x 2n), 128 rows x 128 cols per block, K chunked x32.
// launch_bounds(.,2): cap regs at 128 -> 2 CTAs/SM for latency hiding.
#define LDAB 40   // bf16 row stride (80 B): conflict-free ldmatrix phases
__global__ void __launch_bounds__(256, 2) k_gemm_mma(const float* __restrict__ X, int layer) {
    __shared__ __align__(16) __nv_bfloat16 sAh[128][LDAB];
    __shared__ __align__(16) __nv_bfloat16 sAl[128][LDAB];
    __shared__ __align__(16) __nv_bfloat16 sBh[128][LDAB];
    __shared__ __align__(16) __nv_bfloat16 sBl[128][LDAB];
    int tid = threadIdx.x, lane = tid & 31, wid = tid >> 5;
    int row0 = blockIdx.x * 128;
    int m_base = (wid & 3) * 32;
    int n_base = (wid >> 2) * 64;
    const __nv_bfloat16* wth = g_wth + (size_t)layer * DD * DD;
    const __nv_bfloat16* wtl = g_wtl + (size_t)layer * DD * DD;

    float acc[2][8][4];
    #pragma unroll
    for (int i = 0; i < 2; i++)
        #pragma unroll
        for (int j = 0; j < 8; j++)
            #pragma unroll
            for (int q = 0; q < 4; q++) acc[i][j][q] = 0.f;

    // per-lane ldmatrix base addresses
    int li = lane & 7, mi = lane >> 3;
    uint32_t aAh = smem_u32(&sAh[m_base + (mi & 1) * 8 + li][(mi >> 1) * 8]);
    uint32_t aAl = smem_u32(&sAl[m_base + (mi & 1) * 8 + li][(mi >> 1) * 8]);
    uint32_t aBh = smem_u32(&sBh[n_base + (mi >> 1) * 8 + li][(mi & 1) * 8]);
    uint32_t aBl = smem_u32(&sBl[n_base + (mi >> 1) * 8 + li][(mi & 1) * 8]);

    const float4* X4 = (const float4*)X;
    for (int kc = 0; kc < 4; kc++) {
        __syncthreads();
        // A: load 128x32 fp32 chunk, convert to bf16 hi/lo
        #pragma unroll
        for (int it = 0; it < 4; it++) {
            int t4 = tid + it * 256;            // 1024 float4
            int r = t4 >> 3, c4 = t4 & 7;
            int m = row0 + r;
            float4 v = make_float4(0.f, 0.f, 0.f, 0.f);
            if (m < NN) v = X4[(size_t)m * 32 + kc * 8 + c4];
            uint2 hi, lo;
            hi.x = pack2(v.x, v.y);  hi.y = pack2(v.z, v.w);
            lo.x = pack2lo(v.x, v.y); lo.y = pack2lo(v.z, v.w);
            *(uint2*)((char*)&sAh[0][0] + r * (LDAB * 2) + c4 * 8) = hi;
            *(uint2*)((char*)&sAl[0][0] + r * (LDAB * 2) + c4 * 8) = lo;
        }
        // B: linear copy of pre-transposed images
        #pragma unroll
        for (int it = 0; it < 2; it++) {
            int t2 = tid + it * 256;            // 512 uint4
            int n = t2 >> 2, q = t2 & 3;
            *(uint4*)((char*)&sBh[0][0] + n * (LDAB * 2) + q * 16) =
                ((const uint4*)wth)[n * 16 + kc * 4 + q];
            *(uint4*)((char*)&sBl[0][0] + n * (LDAB * 2) + q * 16) =
                ((const uint4*)wtl)[n * 16 + kc * 4 + q];
        }
        __syncthreads();

        #pragma unroll
        for (int ks = 0; ks < 2; ks++) {
            int k0b = ks * 32;                  // bytes (16 bf16)
            uint32_t ah[2][4], al[2][4];
            ldsm4(ah[0], aAh + k0b);
            ldsm4(ah[1], aAh + 16 * (LDAB * 2) + k0b);
            ldsm4(al[0], aAl + k0b);
            ldsm4(al[1], aAl + 16 * (LDAB * 2) + k0b);
            #pragma unroll
            for (int grp = 0; grp < 2; grp++) {
                uint32_t bh[4][2], bl[4][2];
                uint32_t off = grp * 32 * (LDAB * 2) + k0b;
                ldsm4(&bh[0][0], aBh + off);
                ldsm4(&bh[2][0], aBh + off + 16 * (LDAB * 2));
                ldsm4(&bl[0][0], aBl + off);
                ldsm4(&bl[2][0], aBl + off + 16 * (LDAB * 2));
                #pragma unroll
                for (int mt = 0; mt < 2; mt++)
                    #pragma unroll
                    for (int nt = 0; nt < 4; nt++) {
                        float* c = acc[mt][grp * 4 + nt];
                        mma_bf16(c, ah[mt], bh[nt]);
                        mma_bf16(c, al[mt], bh[nt]);
                        mma_bf16(c, ah[mt], bl[nt]);
                    }
            }
        }
    }

    // epilogue: fragment (c0,c1)@(g,tig*2), (c2,c3)@(g+8,tig*2)
    int g = lane >> 2, tig = lane & 3;
    #pragma unroll
    for (int mt = 0; mt < 2; mt++)
        #pragma unroll
        for (int nt = 0; nt < 8; nt++) {
            float* c = acc[mt][nt];
            int m0 = row0 + m_base + mt * 16 + g;
            int col = n_base + nt * 8 + tig * 2;
            if (m0 < NN)
                *(float2*)&g_h[(size_t)m0 * DD + col] = make_float2(c[0], c[1]);
            if (m0 + 8 < NN)
                *(float2*)&g_h[(size_t)(m0 + 8) * DD + col] = make_float2(c[2], c[3]);
        }
}

// ---------------- SpMM: g_h2[d] = bias + selfw*h[d] + sum_e w[e]*h[col[e]] ----------------
// 8-edge unroll: 8 in-flight 128B gathers per warp.
__global__ void k_spmm(const float* __restrict__ bias) {
    int n    = (blockIdx.x * blockDim.x + threadIdx.x) >> 5;
    int lane = threadIdx.x & 31;
    if (n >= NN) return;
    const float4* h4 = (const float4*)g_h;
    float4 acc = ((const float4*)bias)[lane];
    float dn = g_dis[n];
    float sw = dn * dn;
    float4 hv = h4[(size_t)n * 32 + lane];
    acc.x = fmaf(sw, hv.x, acc.x);
    acc.y = fmaf(sw, hv.y, acc.y);
    acc.z = fmaf(sw, hv.z, acc.z);
    acc.w = fmaf(sw, hv.w, acc.w);
    int s = g_rowptr[n], e = g_rowptr[n + 1];
    int i = s;
    for (; i + 8 <= e; i += 8) {
        int   c0 = g_col[i],     c1 = g_col[i + 1];
        int   c2 = g_col[i + 2], c3 = g_col[i + 3];
        int   c4 = g_col[i + 4], c5 = g_col[i + 5];
        int   c6 = g_col[i + 6], c7 = g_col[i + 7];
        float w0 = g_we[i],      w1 = g_we[i + 1];
        float w2 = g_we[i + 2],  w3 = g_we[i + 3];
        float w4 = g_we[i + 4],  w5 = g_we[i + 5];
        float w6 = g_we[i + 6],  w7 = g_we[i + 7];
        float4 v0 = h4[(size_t)c0 * 32 + lane];
        float4 v1 = h4[(size_t)c1 * 32 + lane];
        float4 v2 = h4[(size_t)c2 * 32 + lane];
        float4 v3 = h4[(size_t)c3 * 32 + lane];
        float4 v4 = h4[(size_t)c4 * 32 + lane];
        float4 v5 = h4[(size_t)c5 * 32 + lane];
        float4 v6 = h4[(size_t)c6 * 32 + lane];
        float4 v7 = h4[(size_t)c7 * 32 + lane];
        acc.x = fmaf(w0, v0.x, acc.x); acc.y = fmaf(w0, v0.y, acc.y);
        acc.z = fmaf(w0, v0.z, acc.z); acc.w = fmaf(w0, v0.w, acc.w);
        acc.x = fmaf(w1, v1.x, acc.x); acc.y = fmaf(w1, v1.y, acc.y);
        acc.z = fmaf(w1, v1.z, acc.z); acc.w = fmaf(w1, v1.w, acc.w);
        acc.x = fmaf(w2, v2.x, acc.x); acc.y = fmaf(w2, v2.y, acc.y);
        acc.z = fmaf(w2, v2.z, acc.z); acc.w = fmaf(w2, v2.w, acc.w);
        acc.x = fmaf(w3, v3.x, acc.x); acc.y = fmaf(w3, v3.y, acc.y);
        acc.z = fmaf(w3, v3.z, acc.z); acc.w = fmaf(w3, v3.w, acc.w);
        acc.x = fmaf(w4, v4.x, acc.x); acc.y = fmaf(w4, v4.y, acc.y);
        acc.z = fmaf(w4, v4.z, acc.z); acc.w = fmaf(w4, v4.w, acc.w);
        acc.x = fmaf(w5, v5.x, acc.x); acc.y = fmaf(w5, v5.y, acc.y);
        acc.z = fmaf(w5, v5.z, acc.z); acc.w = fmaf(w5, v5.w, acc.w);
        acc.x = fmaf(w6, v6.x, acc.x); acc.y = fmaf(w6, v6.y, acc.y);
        acc.z = fmaf(w6, v6.z, acc.z); acc.w = fmaf(w6, v6.w, acc.w);
        acc.x = fmaf(w7, v7.x, acc.x); acc.y = fmaf(w7, v7.y, acc.y);
        acc.z = fmaf(w7, v7.z, acc.z); acc.w = fmaf(w7, v7.w, acc.w);
    }
    for (; i < e; i++) {
        int c0 = g_col[i]; float w0 = g_we[i];
        float4 v0 = h4[(size_t)c0 * 32 + lane];
        acc.x = fmaf(w0, v0.x, acc.x); acc.y = fmaf(w0, v0.y, acc.y);
        acc.z = fmaf(w0, v0.z, acc.z); acc.w = fmaf(w0, v0.w, acc.w);
    }
    ((float4*)g_h2)[(size_t)n * 32 + lane] = acc;
}

// ---------------- GraphNorm stats: one pass, grid (GG, 4 feature-chunks) ----------------
__global__ void __launch_bounds__(256) k_stats(const float* __restrict__ alpha,
                                               const float* __restrict__ gw) {
    int g = blockIdx.x;
    int fc = blockIdx.y;
    int t = threadIdx.x;
    int f = fc * 32 + (t & 31), sl = t >> 5;
    int s = g_gptr[g], e = g_gptr[g + 1];
    int cnt = e - s;
    __shared__ float ssum[8][32], ssq[8][32];
    float sum = 0.f, sq = 0.f;
    const float* p = g_h2 + (size_t)s * DD + f;
    #pragma unroll 4
    for (int n = sl; n < cnt; n += 8) {
        float v = p[(size_t)n * DD];
        sum += v; sq = fmaf(v, v, sq);
    }
    ssum[sl][t & 31] = sum; ssq[sl][t & 31] = sq;
    __syncthreads();
    if (t < 32) {
        if (cnt <= 0) { g_am[g * DD + f] = 0.f; g_wr[g * DD + f] = 0.f; return; }
        float S = 0.f, Q = 0.f;
        #pragma unroll
        for (int i = 0; i < 8; i++) { S += ssum[i][t]; Q += ssq[i][t]; }
        float inv = 1.f / (float)cnt;
        float mean = S * inv;
        float am = alpha[f] * mean;
        float var = fmaf(am, am, fmaf(-2.f * am, mean, Q * inv));
        g_am[g * DD + f] = am;
        g_wr[g * DD + f] = gw[f] * rsqrtf(var + EPSV);
    }
}

// ---------------- normalize + ELU + residual -> out (x) ----------------
__global__ void k_apply(const float* __restrict__ xres, const float* __restrict__ gnb,
                        float* __restrict__ out) {
    int t = blockIdx.x * blockDim.x + threadIdx.x;
    if (t >= NN * 32) return;
    int n = t >> 5, q = t & 31;
    int g = g_batch[n];
    float4 h = ((const float4*)g_h2)[t];
    float4 a = ((const float4*)g_am)[g * 32 + q];
    float4 w = ((const float4*)g_wr)[g * 32 + q];
    float4 b = ((const float4*)gnb)[q];
    float4 r = ((const float4*)xres)[t];
    float4 o;
    float v;
    v = (h.x - a.x) * w.x + b.x; o.x = (v > 0.f ? v : expm1f(v)) + r.x;
    v = (h.y - a.y) * w.y + b.y; o.y = (v > 0.f ? v : expm1f(v)) + r.y;
    v = (h.z - a.z) * w.z + b.z; o.z = (v > 0.f ? v : expm1f(v)) + r.z;
    v = (h.w - a.w) * w.w + b.w; o.w = (v > 0.f ? v : expm1f(v)) + r.w;
    ((float4*)out)[t] = o;
}

// ---------------- global add pool: grid (GG, 4 chunks) x 256 ----------------
__global__ void __launch_bounds__(256) k_pool(const float* __restrict__ x) {
    int g = blockIdx.x;
    int fc = blockIdx.y;
    int t = threadIdx.x;
    int f = fc * 32 + (t & 31), sl = t >> 5;
    int s = g_gptr[g], e = g_gptr[g + 1];
    int cnt = e - s;
    __shared__ float ssum[8][32];
    float sum = 0.f;
    const float* p = x + (size_t)s * DD + f;
    #pragma unroll 4
    for (int n = sl; n < cnt; n += 8) sum += p[(size_t)n * DD];
    ssum[sl][t & 31] = sum;
    __syncthreads();
    if (t < 32) {
        float S = 0.f;
        #pragma unroll
        for (int i = 0; i < 8; i++) S += ssum[i][t];
        g_pool[g * DD + f] = S;
    }
}

// ---------------- MLP head (reads g_pool) ----------------
__global__ void k_mlp(const float* __restrict__ w1, const float* __restrict__ b1,
                      const float* __restrict__ bng, const float* __restrict__ bnb,
                      const float* __restrict__ bnm, const float* __restrict__ bnv,
                      const float* __restrict__ w2, const float* __restrict__ b2,
                      float* __restrict__ out) {
    int g = blockIdx.x, d = threadIdx.x;
    __shared__ float p[DD], z1[DD];
    p[d] = g_pool[g * DD + d];
    __syncthreads();
    float z = b1[d];
    #pragma unroll 4
    for (int k = 0; k < DD; k++) z = fmaf(p[k], w1[k * DD + d], z);
    z = bng[d] * (z - bnm[d]) * rsqrtf(bnv[d] + EPSV) + bnb[d];
    z = z > 0.f ? z : 0.f;
    z1[d] = z;
    __syncthreads();
    if (d < NCLS) {
        float o = b2[d];
        #pragma unroll 4
        for (int k = 0; k < DD; k++) o = fmaf(z1[k], w2[k * NCLS + d], o);
        out[(size_t)NN * DD + g * NCLS + d] = o;
    }
}

// ---------------- launch ----------------
extern "C" void kernel_launch(void* const* d_in, const int* in_sizes, int n_in,
                              void* d_out, int out_size) {
    const float* x0     = (const float*)d_in[0];
    const void*  ei     = d_in[1];
    const void*  batch  = d_in[2];
    const float* conv_w = (const float*)d_in[3];
    const float* conv_b = (const float*)d_in[4];
    const float* gn_w   = (const float*)d_in[5];
    const float* gn_b   = (const float*)d_in[6];
    const float* gn_ms  = (const float*)d_in[7];
    const float* w1     = (const float*)d_in[8];
    const float* b1     = (const float*)d_in[9];
    const float* bng    = (const float*)d_in[10];
    const float* bnb    = (const float*)d_in[11];
    const float* bnm    = (const float*)d_in[12];
    const float* bnv    = (const float*)d_in[13];
    const float* w2     = (const float*)d_in[14];
    const float* b2     = (const float*)d_in[15];
    float* out = (float*)d_out;

    const int GEMM_GRID = (NN + 127) / 128;

    // layer-0 GEMM at launch slot 4 so ncu profiles it.
    k_setup<<<256, 256>>>((const int*)ei);
    k_wconv_all<<<dim3(64, LL), 256>>>(conv_w);
    k_hist<<<(EE + 255) / 256, 256>>>(ei);
    k_gemm_mma<<<GEMM_GRID, 256>>>(x0, 0);
    k_cvt_batch<<<(NN + 255) / 256, 256>>>(batch);
    k_scan1<<<NB, 256>>>();
    k_scan2<<<1, 32>>>();
    k_scan3<<<NB, 256>>>();
    k_scatter<<<(EE + 255) / 256, 256>>>(ei);

    const float* xin = x0;
    for (int l = 0; l < LL; l++) {
        if (l > 0) k_gemm_mma<<<GEMM_GRID, 256>>>(xin, l);
        k_spmm<<<(NN + 7) / 8, 256>>>(conv_b + (size_t)l * DD);
        k_stats<<<dim3(GG, 4), 256>>>(gn_ms + (size_t)l * DD, gn_w + (size_t)l * DD);
        k_apply<<<(NN * 32 + 255) / 256, 256>>>(xin, gn_b + (size_t)l * DD, out);
        xin = out;
    }
    k_pool<<<dim3(GG, 4), 256>>>(out);
    k_mlp<<<GG, DD>>>(w1, b1, bng, bnb, bnm, bnv, w2, b2, out);
}